// round 2
// baseline (speedup 1.0000x reference)
#include <cuda_runtime.h>
#include <cuda_bf16.h>

#define GRID_N 64
#define NSAMP 128
#define HDIM 64

#define AMINX (-1.25f)
#define AMINY (-1.55f)
#define AMINZ (-1.25f)
#define SCALE (2.5f)   // AABB_MAX - AABB_MIN, all dims

__global__ __launch_bounds__(128) void render_kernel(
    const float* __restrict__ rays_o, const float* __restrict__ rays_d,
    const float* __restrict__ near_, const float* __restrict__ far_,
    const float* __restrict__ jitter, const float* __restrict__ density,
    const float* __restrict__ W1, const float* __restrict__ b1,
    const float* __restrict__ W2, const float* __restrict__ b2,
    const float* __restrict__ Wsig, const float* __restrict__ bsig,
    const float* __restrict__ Wrgb, const float* __restrict__ brgb,
    float* __restrict__ out)
{
    __shared__ float W1s[3 * HDIM];
    __shared__ float b1s[HDIM];
    __shared__ float W2Ts[HDIM * HDIM];   // transposed: [k][j]
    __shared__ float b2s[HDIM];
    __shared__ float Wsigs[HDIM];
    __shared__ float Wrgbs[HDIM * 3];
    __shared__ float bsig_s;
    __shared__ float brgb_s[3];
    __shared__ float pts_s[NSAMP * 3];
    __shared__ float sigma_s[NSAMP];
    __shared__ float rgb_s[NSAMP * 3];
    __shared__ float scan_s[NSAMP];
    __shared__ int   compact_s[NSAMP];
    __shared__ int   warpcnt[4];
    __shared__ float red_s[12];

    const int tid = threadIdx.x;
    const int n   = blockIdx.x;

    // ---- stage weights into smem (W2 transposed for contiguous j-reads) ----
    #pragma unroll 4
    for (int i = tid; i < HDIM * HDIM; i += 128) {
        int k = i >> 6, j = i & 63;
        W2Ts[i] = W2[(j << 6) + k];       // W2T[k][j] = W2[j][k]
    }
    for (int i = tid; i < 3 * HDIM; i += 128) {
        W1s[i]   = W1[i];
        Wrgbs[i] = Wrgb[i];
    }
    if (tid < HDIM) {
        b1s[tid]   = b1[tid];
        b2s[tid]   = b2[tid];
        Wsigs[tid] = Wsig[tid];
    }
    if (tid == 0) bsig_s = bsig[0];
    if (tid < 3)  brgb_s[tid] = brgb[tid];

    // ---- phase A: sampling + grid mask (exact-rounded to match reference) ----
    const float ox = rays_o[3 * n + 0], oy = rays_o[3 * n + 1], oz = rays_o[3 * n + 2];
    const float dx = rays_d[3 * n + 0], dy = rays_d[3 * n + 1], dz = rays_d[3 * n + 2];
    const float nr = near_[n], fr = far_[n];
    const float step = __fmul_rn(__fsub_rn(fr, nr), 0.0078125f);   // /128 exact

    float z = __fadd_rn(nr, __fmul_rn((float)tid, step));
    // pts0 = o + z*d  (mul then add, no fma: match JAX bit pattern at floor boundary)
    float p0x = __fadd_rn(ox, __fmul_rn(z, dx));
    float p0y = __fadd_rn(oy, __fmul_rn(z, dy));
    float p0z = __fadd_rn(oz, __fmul_rn(z, dz));
    float ux = __fmul_rn(__fdiv_rn(__fsub_rn(p0x, AMINX), SCALE), (float)GRID_N);
    float uy = __fmul_rn(__fdiv_rn(__fsub_rn(p0y, AMINY), SCALE), (float)GRID_N);
    float uz = __fmul_rn(__fdiv_rn(__fsub_rn(p0z, AMINZ), SCALE), (float)GRID_N);
    int ix = (int)floorf(ux);
    int iy = (int)floorf(uy);
    int iz = (int)floorf(uz);
    bool inb = (ix >= 0) & (ix < GRID_N) & (iy >= 0) & (iy < GRID_N) & (iz >= 0) & (iz < GRID_N);
    bool mask = false;
    if (inb) {
        float dv = density[(ix << 12) + (iy << 6) + iz];
        mask = dv > 0.5f;
    }
    // jittered z (z>0 always when mask; masked z_val irrelevant)
    float zbase = mask ? z : 0.0f;
    float jit = jitter[n * NSAMP + tid];
    float zv = __fadd_rn(zbase, __fmul_rn(jit, step));
    pts_s[tid * 3 + 0] = __fadd_rn(ox, __fmul_rn(zv, dx));
    pts_s[tid * 3 + 1] = __fadd_rn(oy, __fmul_rn(zv, dy));
    pts_s[tid * 3 + 2] = __fadd_rn(oz, __fmul_rn(zv, dz));

    // ---- compaction: active-sample list ----
    unsigned bal = __ballot_sync(0xffffffffu, mask);
    int lane = tid & 31, w = tid >> 5;
    int pre = __popc(bal & ((1u << lane) - 1u));
    if (lane == 0) warpcnt[w] = __popc(bal);
    __syncthreads();
    int base = 0;
    #pragma unroll
    for (int i = 0; i < 4; i++) if (i < w) base += warpcnt[i];
    if (mask) compact_s[base + pre] = tid;
    int total = warpcnt[0] + warpcnt[1] + warpcnt[2] + warpcnt[3];
    __syncthreads();

    // ---- phase B: MLP on compacted samples only ----
    if (tid < total) {
        int slot = compact_s[tid];
        float px = pts_s[slot * 3 + 0];
        float py = pts_s[slot * 3 + 1];
        float pz = pts_s[slot * 3 + 2];

        float h1[HDIM];
        #pragma unroll
        for (int k = 0; k < HDIM; k++) {
            float a = fmaf(px, W1s[k], fmaf(py, W1s[HDIM + k], fmaf(pz, W1s[2 * HDIM + k], b1s[k])));
            h1[k] = fmaxf(a, 0.0f);
        }

        float sig = bsig_s;
        float r0 = brgb_s[0], r1 = brgb_s[1], r2 = brgb_s[2];
        #pragma unroll 4
        for (int k = 0; k < HDIM; k += 2) {
            float acca = b2s[k];
            float accb = b2s[k + 1];
            const float4* wa = reinterpret_cast<const float4*>(&W2Ts[k << 6]);
            const float4* wb = reinterpret_cast<const float4*>(&W2Ts[(k + 1) << 6]);
            #pragma unroll
            for (int q = 0; q < 16; q++) {
                float4 va = wa[q];
                float4 vb = wb[q];
                acca = fmaf(h1[4 * q + 0], va.x, acca);
                acca = fmaf(h1[4 * q + 1], va.y, acca);
                acca = fmaf(h1[4 * q + 2], va.z, acca);
                acca = fmaf(h1[4 * q + 3], va.w, acca);
                accb = fmaf(h1[4 * q + 0], vb.x, accb);
                accb = fmaf(h1[4 * q + 1], vb.y, accb);
                accb = fmaf(h1[4 * q + 2], vb.z, accb);
                accb = fmaf(h1[4 * q + 3], vb.w, accb);
            }
            float h2a = fmaxf(acca, 0.0f);
            float h2b = fmaxf(accb, 0.0f);
            sig = fmaf(h2a, Wsigs[k], sig);
            r0  = fmaf(h2a, Wrgbs[3 * k + 0], r0);
            r1  = fmaf(h2a, Wrgbs[3 * k + 1], r1);
            r2  = fmaf(h2a, Wrgbs[3 * k + 2], r2);
            sig = fmaf(h2b, Wsigs[k + 1], sig);
            r0  = fmaf(h2b, Wrgbs[3 * k + 3], r0);
            r1  = fmaf(h2b, Wrgbs[3 * k + 4], r1);
            r2  = fmaf(h2b, Wrgbs[3 * k + 5], r2);
        }
        sigma_s[slot] = sig;
        // sigmoid
        rgb_s[slot * 3 + 0] = 1.0f / (1.0f + __expf(-r0));
        rgb_s[slot * 3 + 1] = 1.0f / (1.0f + __expf(-r1));
        rgb_s[slot * 3 + 2] = 1.0f / (1.0f + __expf(-r2));
    }
    __syncthreads();

    // ---- phase C: composite ----
    float alpha = 0.0f;
    if (mask) {
        float s = sigma_s[tid];
        float tau = fmaxf(s, 0.0f) * step;
        alpha = 1.0f - __expf(-tau);
    }
    scan_s[tid] = 1.0f - alpha + 1e-10f;
    __syncthreads();
    // inclusive product scan (Hillis-Steele)
    #pragma unroll
    for (int off = 1; off < NSAMP; off <<= 1) {
        float y = (tid >= off) ? scan_s[tid - off] : 1.0f;
        __syncthreads();
        scan_s[tid] *= y;
        __syncthreads();
    }
    float Tprev = (tid == 0) ? 1.0f : scan_s[tid - 1];
    float wgt = alpha * Tprev;
    float c0 = 0.0f, c1 = 0.0f, c2 = 0.0f;
    if (mask) {
        c0 = wgt * rgb_s[tid * 3 + 0];
        c1 = wgt * rgb_s[tid * 3 + 1];
        c2 = wgt * rgb_s[tid * 3 + 2];
    }
    // warp reduce
    #pragma unroll
    for (int off = 16; off > 0; off >>= 1) {
        c0 += __shfl_down_sync(0xffffffffu, c0, off);
        c1 += __shfl_down_sync(0xffffffffu, c1, off);
        c2 += __shfl_down_sync(0xffffffffu, c2, off);
    }
    if (lane == 0) {
        red_s[w * 3 + 0] = c0;
        red_s[w * 3 + 1] = c1;
        red_s[w * 3 + 2] = c2;
    }
    __syncthreads();
    if (tid == 0) {
        float nohit = scan_s[NSAMP - 1];
        float o0 = red_s[0] + red_s[3] + red_s[6] + red_s[9] + nohit;
        float o1 = red_s[1] + red_s[4] + red_s[7] + red_s[10] + nohit;
        float o2 = red_s[2] + red_s[5] + red_s[8] + red_s[11] + nohit;
        out[n * 3 + 0] = o0;
        out[n * 3 + 1] = o1;
        out[n * 3 + 2] = o2;
    }
}

extern "C" void kernel_launch(void* const* d_in, const int* in_sizes, int n_in,
                              void* d_out, int out_size) {
    const float* rays_o  = (const float*)d_in[0];
    const float* rays_d  = (const float*)d_in[1];
    const float* near_   = (const float*)d_in[2];
    const float* far_    = (const float*)d_in[3];
    const float* jitter  = (const float*)d_in[4];
    const float* density = (const float*)d_in[5];
    const float* W1   = (const float*)d_in[6];
    const float* b1   = (const float*)d_in[7];
    const float* W2   = (const float*)d_in[8];
    const float* b2   = (const float*)d_in[9];
    const float* Wsig = (const float*)d_in[10];
    const float* bsig = (const float*)d_in[11];
    const float* Wrgb = (const float*)d_in[12];
    const float* brgb = (const float*)d_in[13];
    float* out = (float*)d_out;

    int N = in_sizes[2];   // near has N elements
    render_kernel<<<N, 128>>>(rays_o, rays_d, near_, far_, jitter, density,
                              W1, b1, W2, b2, Wsig, bsig, Wrgb, brgb, out);
}

// round 5
// speedup vs baseline: 3.2454x; 3.2454x over previous
#include <cuda_runtime.h>
#include <cuda_bf16.h>

#define GRID_N 64
#define NSAMP 128
#define HDIM 64
#define NRAY_MAX 8192
#define NSAMP_TOT (NRAY_MAX * NSAMP)

#define AMINX (-1.25f)
#define AMINY (-1.55f)
#define AMINZ (-1.25f)
#define SCALE (2.5f)

// ---- scratch (device globals; zero-init at module load) ----
__device__ float4   g_list[NSAMP_TOT];     // {x,y,z, id-as-float-bits} compacted active samples
__device__ float4   g_rgbsig[NSAMP_TOT];   // {r,g,b,sigma} per sample id (only active ids written)
__device__ unsigned g_maskbits[NRAY_MAX * 4];
__device__ int      g_count;

// ============================================================
// K1: sampling + occupancy-grid mask + global compaction
//     512 threads = 4 rays per CTA (one atomic per CTA)
// ============================================================
__global__ __launch_bounds__(512) void k1_sample(
    const float* __restrict__ rays_o, const float* __restrict__ rays_d,
    const float* __restrict__ near_, const float* __restrict__ far_,
    const float* __restrict__ jitter, const float* __restrict__ density,
    int N)
{
    __shared__ int warpcnt[16];
    __shared__ int base_s;

    const int tid  = threadIdx.x;
    const int w    = tid >> 5;            // warp 0..15
    const int lane = tid & 31;
    const int r    = tid >> 7;            // ray within CTA 0..3
    const int s    = tid & 127;           // sample 0..127
    const int n    = blockIdx.x * 4 + r;
    const bool valid = (n < N);

    bool mask = false;
    float px = 0.f, py = 0.f, pz = 0.f;

    if (valid) {
        const float ox = rays_o[3 * n + 0], oy = rays_o[3 * n + 1], oz = rays_o[3 * n + 2];
        const float dx = rays_d[3 * n + 0], dy = rays_d[3 * n + 1], dz = rays_d[3 * n + 2];
        const float nr = near_[n], fr = far_[n];
        const float step = __fmul_rn(__fsub_rn(fr, nr), 0.0078125f);  // /128 exact

        float z = __fadd_rn(nr, __fmul_rn((float)s, step));
        // exact-rounded (no fma) to match JAX bit pattern at floor boundaries
        float p0x = __fadd_rn(ox, __fmul_rn(z, dx));
        float p0y = __fadd_rn(oy, __fmul_rn(z, dy));
        float p0z = __fadd_rn(oz, __fmul_rn(z, dz));
        float ux = __fmul_rn(__fdiv_rn(__fsub_rn(p0x, AMINX), SCALE), (float)GRID_N);
        float uy = __fmul_rn(__fdiv_rn(__fsub_rn(p0y, AMINY), SCALE), (float)GRID_N);
        float uz = __fmul_rn(__fdiv_rn(__fsub_rn(p0z, AMINZ), SCALE), (float)GRID_N);
        int ix = (int)floorf(ux);
        int iy = (int)floorf(uy);
        int iz = (int)floorf(uz);
        bool inb = (ix >= 0) & (ix < GRID_N) & (iy >= 0) & (iy < GRID_N)
                 & (iz >= 0) & (iz < GRID_N);
        if (inb) {
            float dv = density[(ix << 12) + (iy << 6) + iz];
            mask = dv > 0.5f;
        }
        float zbase = mask ? z : 0.0f;
        float jit = jitter[n * NSAMP + s];
        float zv = __fadd_rn(zbase, __fmul_rn(jit, step));
        px = __fadd_rn(ox, __fmul_rn(zv, dx));
        py = __fadd_rn(oy, __fmul_rn(zv, dy));
        pz = __fadd_rn(oz, __fmul_rn(zv, dz));
    }

    unsigned bal = __ballot_sync(0xffffffffu, mask);
    int pre = __popc(bal & ((1u << lane) - 1u));
    if (lane == 0) {
        warpcnt[w] = __popc(bal);
        if (valid) g_maskbits[n * 4 + (w & 3)] = bal;
    }
    __syncthreads();
    if (tid == 0) {
        int total = 0;
        #pragma unroll
        for (int i = 0; i < 16; i++) total += warpcnt[i];
        base_s = atomicAdd(&g_count, total);
    }
    int wbase = 0;
    #pragma unroll
    for (int i = 0; i < 16; i++) if (i < w) wbase += warpcnt[i];
    __syncthreads();

    if (mask) {
        int pos = base_s + wbase + pre;
        g_list[pos] = make_float4(px, py, pz, __int_as_float(n * NSAMP + s));
    }
}

// ============================================================
// K2: dense batched MLP over the compacted sample list
//     packed f32x2 FFMA2, weights staged once per CTA
// ============================================================
__global__ __launch_bounds__(128, 4) void k2_mlp(
    const float* __restrict__ W1, const float* __restrict__ b1,
    const float* __restrict__ W2, const float* __restrict__ b2,
    const float* __restrict__ Wsig, const float* __restrict__ bsig,
    const float* __restrict__ Wrgb, const float* __restrict__ brgb)
{
    __shared__ __align__(16) float W2Ts[HDIM * HDIM];  // W2T[k][j] = W2[j][k]
    __shared__ float W1s[3 * HDIM];
    __shared__ float b1s[HDIM];
    __shared__ float b2s[HDIM];
    __shared__ float4 Wos[HDIM];   // {Wrgb0, Wrgb1, Wrgb2, Wsig} per column
    __shared__ float  bias4[4];    // {brgb0, brgb1, brgb2, bsig}

    const int tid = threadIdx.x;

    #pragma unroll 4
    for (int i = tid; i < HDIM * HDIM; i += 128) {
        int k = i >> 6, j = i & 63;
        W2Ts[i] = W2[(j << 6) + k];
    }
    for (int i = tid; i < 3 * HDIM; i += 128) W1s[i] = W1[i];
    if (tid < HDIM) {
        b1s[tid] = b1[tid];
        b2s[tid] = b2[tid];
        Wos[tid] = make_float4(Wrgb[3 * tid + 0], Wrgb[3 * tid + 1],
                               Wrgb[3 * tid + 2], Wsig[tid]);
    }
    if (tid < 3) bias4[tid] = brgb[tid];
    if (tid == 3) bias4[3] = bsig[0];
    __syncthreads();

    const int total  = g_count;
    const int stride = gridDim.x * 128;

    for (int i = blockIdx.x * 128 + tid; i < total; i += stride) {
        float4 e = g_list[i];
        const float px = e.x, py = e.y, pz = e.z;
        const int id = __float_as_int(e.w);

        // ---- layer 1: 3 -> 64, pack pairs for f32x2 ----
        unsigned long long h1p[HDIM / 2];
        #pragma unroll
        for (int k = 0; k < HDIM; k += 2) {
            float a = fmaf(px, W1s[k],     fmaf(py, W1s[HDIM + k],     fmaf(pz, W1s[2 * HDIM + k],     b1s[k])));
            float b = fmaf(px, W1s[k + 1], fmaf(py, W1s[HDIM + k + 1], fmaf(pz, W1s[2 * HDIM + k + 1], b1s[k + 1])));
            a = fmaxf(a, 0.0f);
            b = fmaxf(b, 0.0f);
            asm("mov.b64 %0, {%1, %2};" : "=l"(h1p[k >> 1]) : "f"(a), "f"(b));
        }

        // ---- layer 2 + heads, fused ----
        float r0 = bias4[0], r1 = bias4[1], r2 = bias4[2], sig = bias4[3];
        #pragma unroll 4
        for (int k = 0; k < HDIM; k++) {
            unsigned long long acc;
            asm("mov.b64 %0, {%1, %2};" : "=l"(acc) : "f"(b2s[k]), "f"(0.0f));
            const ulonglong2* wr = reinterpret_cast<const ulonglong2*>(&W2Ts[k << 6]);
            #pragma unroll
            for (int q = 0; q < 16; q++) {
                ulonglong2 v = wr[q];
                asm("fma.rn.f32x2 %0, %1, %2, %0;" : "+l"(acc) : "l"(h1p[2 * q + 0]), "l"(v.x));
                asm("fma.rn.f32x2 %0, %1, %2, %0;" : "+l"(acc) : "l"(h1p[2 * q + 1]), "l"(v.y));
            }
            float lo, hi;
            asm("mov.b64 {%0, %1}, %2;" : "=f"(lo), "=f"(hi) : "l"(acc));
            float h2 = fmaxf(lo + hi, 0.0f);
            float4 wo = Wos[k];
            r0  = fmaf(h2, wo.x, r0);
            r1  = fmaf(h2, wo.y, r1);
            r2  = fmaf(h2, wo.z, r2);
            sig = fmaf(h2, wo.w, sig);
        }

        float4 outv;
        outv.x = 1.0f / (1.0f + __expf(-r0));
        outv.y = 1.0f / (1.0f + __expf(-r1));
        outv.z = 1.0f / (1.0f + __expf(-r2));
        outv.w = sig;
        g_rgbsig[id] = outv;
    }
}

// ============================================================
// K3: per-ray composite (shuffle product scan)
// ============================================================
__global__ __launch_bounds__(128) void k3_composite(
    const float* __restrict__ near_, const float* __restrict__ far_,
    float* __restrict__ out)
{
    __shared__ float wtot[4];
    __shared__ float red[12];

    const int n    = blockIdx.x;
    const int tid  = threadIdx.x;
    const int lane = tid & 31;
    const int w    = tid >> 5;

    const float step = __fmul_rn(__fsub_rn(far_[n], near_[n]), 0.0078125f);
    const unsigned bal = g_maskbits[n * 4 + w];
    const bool mask = (bal >> lane) & 1u;

    float4 rs = g_rgbsig[n * NSAMP + tid];   // coalesced 16B
    float alpha = 0.0f;
    if (mask) {
        float tau = fmaxf(rs.w, 0.0f) * step;
        alpha = 1.0f - __expf(-tau);
    }
    float f = 1.0f - alpha + 1e-10f;

    // warp inclusive product scan
    float scan = f;
    #pragma unroll
    for (int off = 1; off < 32; off <<= 1) {
        float v = __shfl_up_sync(0xffffffffu, scan, off);
        if (lane >= off) scan *= v;
    }
    if (lane == 31) wtot[w] = scan;
    __syncthreads();
    float prefix = 1.0f;
    #pragma unroll
    for (int i = 0; i < 4; i++) if (i < w) prefix *= wtot[i];

    float excl = __shfl_up_sync(0xffffffffu, scan, 1);
    if (lane == 0) excl = 1.0f;
    float Tprev = excl * prefix;
    float wgt = alpha * Tprev;

    float c0 = 0.f, c1 = 0.f, c2 = 0.f;
    if (mask) {
        c0 = wgt * rs.x;
        c1 = wgt * rs.y;
        c2 = wgt * rs.z;
    }
    #pragma unroll
    for (int off = 16; off > 0; off >>= 1) {
        c0 += __shfl_down_sync(0xffffffffu, c0, off);
        c1 += __shfl_down_sync(0xffffffffu, c1, off);
        c2 += __shfl_down_sync(0xffffffffu, c2, off);
    }
    if (lane == 0) {
        red[w * 3 + 0] = c0;
        red[w * 3 + 1] = c1;
        red[w * 3 + 2] = c2;
    }
    __syncthreads();
    if (tid == 0) {
        float nohit = wtot[0] * wtot[1] * wtot[2] * wtot[3];
        out[n * 3 + 0] = red[0] + red[3] + red[6] + red[9]  + nohit;
        out[n * 3 + 1] = red[1] + red[4] + red[7] + red[10] + nohit;
        out[n * 3 + 2] = red[2] + red[5] + red[8] + red[11] + nohit;
    }
}

extern "C" void kernel_launch(void* const* d_in, const int* in_sizes, int n_in,
                              void* d_out, int out_size) {
    const float* rays_o  = (const float*)d_in[0];
    const float* rays_d  = (const float*)d_in[1];
    const float* near_   = (const float*)d_in[2];
    const float* far_    = (const float*)d_in[3];
    const float* jitter  = (const float*)d_in[4];
    const float* density = (const float*)d_in[5];
    const float* W1   = (const float*)d_in[6];
    const float* b1   = (const float*)d_in[7];
    const float* W2   = (const float*)d_in[8];
    const float* b2   = (const float*)d_in[9];
    const float* Wsig = (const float*)d_in[10];
    const float* bsig = (const float*)d_in[11];
    const float* Wrgb = (const float*)d_in[12];
    const float* brgb = (const float*)d_in[13];
    float* out = (float*)d_out;

    const int N = in_sizes[2];

    void* cnt_addr = nullptr;
    cudaGetSymbolAddress(&cnt_addr, g_count);
    cudaMemsetAsync(cnt_addr, 0, sizeof(int));

    k1_sample<<<(N + 3) / 4, 512>>>(rays_o, rays_d, near_, far_, jitter, density, N);
    k2_mlp<<<1184, 128>>>(W1, b1, W2, b2, Wsig, bsig, Wrgb, brgb);
    k3_composite<<<N, 128>>>(near_, far_, out);
}